// round 13
// baseline (speedup 1.0000x reference)
#include <cuda_runtime.h>
#include <cstdint>

#define NTOK   8192              // B*S
#define T_SLOT 16
#define E_DIM  1024
#define D_DIM  100
#define OUT_W  (E_DIM + D_DIM)   // 1124

__global__ __launch_bounds__(128, 10)
void fuse_triples_flat2_kernel(const int*   __restrict__ inputs,   // [NTOK]
                               const int*   __restrict__ triples,  // [NTOK,T,3]
                               const int*   __restrict__ flags,    // [NTOK,T]
                               const float* __restrict__ emb,      // [VOCAB,1024]
                               const float* __restrict__ ent,      // [ENT_VOCAB,100]
                               float*       __restrict__ out)      // [NTOK,1124]
{
    const int gwarp = (blockIdx.x * blockDim.x + threadIdx.x) >> 5;
    const int lane  = threadIdx.x & 31;
    const int token = gwarp;

    // ---- hop 1: ALL independent loads issued together ----
    const int vrow = inputs[token];

    int f  = 0, t0 = 0, t1 = 0;
    if (lane < T_SLOT) {
        const int slot = token * T_SLOT + lane;
        f  = flags[slot];
        t0 = triples[slot * 3 + 0];     // head (unconditional)
        t1 = triples[slot * 3 + 1];     // tail (unconditional)
    }

    // copy loads depend only on vrow — issue before the gather decode
    const float4* __restrict__ src =
        reinterpret_cast<const float4*>(emb + (size_t)vrow * E_DIM);
    float4 c[8];
    #pragma unroll
    for (int i = 0; i < 8; ++i)
        c[i] = src[lane + 32 * i];

    // ---- ALU-only decode ----
    int e = -1;
    if (lane < T_SLOT) {
        if (f == 1)      e = t1;        // tail entity
        else if (f == 2) e = t0;        // head entity
    }
    const unsigned vmask = __ballot_sync(0xffffffffu, e >= 0);
    const int cnt = __popc(vmask & 0xFFFFu);

    // ---- hop 2: entity gathers (lanes 0..24, one float4 each) ----
    float4 acc = make_float4(0.f, 0.f, 0.f, 0.f);
    #pragma unroll
    for (int j = 0; j < T_SLOT; ++j) {
        const int ej = __shfl_sync(0xffffffffu, e, j);
        if (ej >= 0 && lane < 25) {
            const float4 r = reinterpret_cast<const float4*>(
                                 ent + (size_t)ej * D_DIM)[lane];
            acc.x += r.x; acc.y += r.y; acc.z += r.z; acc.w += r.w;
        }
    }

    // ---- stores (all .cs: keep output out of L2's protected set) ----
    float4* __restrict__ dst =
        reinterpret_cast<float4*>(out + (size_t)token * OUT_W);
    #pragma unroll
    for (int i = 0; i < 8; ++i)
        __stcs(dst + lane + 32 * i, c[i]);

    if (lane < 25) {
        const float inv = 1.0f / (float)(cnt > 0 ? cnt : 1);
        acc.x *= inv; acc.y *= inv; acc.z *= inv; acc.w *= inv;
        __stcs(reinterpret_cast<float4*>(out + (size_t)token * OUT_W + E_DIM) + lane,
               acc);
    }
}

extern "C" void kernel_launch(void* const* d_in, const int* in_sizes, int n_in,
                              void* d_out, int out_size)
{
    const int*   inputs  = (const int*)  d_in[0];
    const int*   triples = (const int*)  d_in[1];
    const int*   flags   = (const int*)  d_in[2];
    const float* emb     = (const float*)d_in[3];
    const float* ent     = (const float*)d_in[4];
    float*       out     = (float*)      d_out;

    // one warp per token: 8192 warps = 2048 blocks * 4 warps
    fuse_triples_flat2_kernel<<<NTOK / 4, 128>>>(inputs, triples, flags,
                                                 emb, ent, out);
}